// round 15
// baseline (speedup 1.0000x reference)
#include <cuda_runtime.h>
#include <cuda_fp16.h>
#include <math.h>
#include <stdint.h>

#define DIM  1024
#define HID  3072
#define MTOK 8192
#define FSCALE (1.0f/127.0f)

// ---------------- device scratch ----------------
__device__ __align__(16) __half g_wg[(size_t)HID*DIM];
__device__ __align__(16) __half g_wu[(size_t)HID*DIM];
__device__ __align__(16) __half g_wd[(size_t)DIM*HID];
__device__ __align__(16) __half g_xh[(size_t)MTOK*DIM];
__device__ __align__(16) __half g_h [(size_t)MTOK*HID];

// ---------------- helpers ----------------
__device__ __forceinline__ uint32_t smem_u32(const void* p){
    uint32_t a;
    asm("{ .reg .u64 t; cvta.to.shared.u64 t, %1; cvt.u32.u64 %0, t; }" : "=r"(a) : "l"(p));
    return a;
}
__device__ __forceinline__ void cp_async16(uint32_t s, const void* g){
    asm volatile("cp.async.cg.shared.global [%0], [%1], 16;" :: "r"(s), "l"(g));
}
#define CP_COMMIT() asm volatile("cp.async.commit_group;" ::: "memory")
#define CP_WAIT(N)  asm volatile("cp.async.wait_group %0;" :: "n"(N) : "memory")

__device__ __forceinline__ void ldsm_x4(uint32_t* r, uint32_t a){
    asm volatile("ldmatrix.sync.aligned.m8n8.x4.shared.b16 {%0,%1,%2,%3}, [%4];"
        : "=r"(r[0]),"=r"(r[1]),"=r"(r[2]),"=r"(r[3]) : "r"(a));
}
__device__ __forceinline__ void mma16816(float* d, const uint32_t* a, const uint32_t* b){
    asm volatile("mma.sync.aligned.m16n8k16.row.col.f32.f16.f16.f32 "
        "{%0,%1,%2,%3},{%4,%5,%6,%7},{%8,%9},{%0,%1,%2,%3};"
        : "+f"(d[0]),"+f"(d[1]),"+f"(d[2]),"+f"(d[3])
        : "r"(a[0]),"r"(a[1]),"r"(a[2]),"r"(a[3]), "r"(b[0]),"r"(b[1]));
}

// ---------------- prep: one launch, grid.y selects tensor ----------------
// y=0: cast x fp32->fp16 (n4 = M*DIM/4)
// y=1: conv wg int32->fp16 (n4 = HID*DIM/4)
// y=2: conv wu
__global__ void k_prep(const float* __restrict__ x, const int* __restrict__ wg,
                       const int* __restrict__ wu,
                       __half* __restrict__ xo, __half* __restrict__ wgo,
                       __half* __restrict__ wuo, int nx4, int nw4)
{
    int i = blockIdx.x * blockDim.x + threadIdx.x;
    if (blockIdx.y == 0){
        if (i < nx4){
            float4 v = ((const float4*)x)[i];
            __half2 a, b;
            a.x = __float2half(v.x); a.y = __float2half(v.y);
            b.x = __float2half(v.z); b.y = __float2half(v.w);
            ((__half2*)xo)[2*i]   = a;
            ((__half2*)xo)[2*i+1] = b;
        }
    } else {
        const int* w = (blockIdx.y == 1) ? wg : wu;
        __half*    o = (blockIdx.y == 1) ? wgo : wuo;
        if (i < nw4){
            int4 v = ((const int4*)w)[i];
            __half2 a, b;
            a.x = __float2half((float)v.x); a.y = __float2half((float)v.y);
            b.x = __float2half((float)v.z); b.y = __float2half((float)v.w);
            ((__half2*)o)[2*i]   = a;
            ((__half2*)o)[2*i+1] = b;
        }
    }
}

// ---------------- GEMM config ----------------
// BK=64 fp16 (128B data rows + 16B pad = 144B stride, conflict-free ldmatrix).
static constexpr int ROWB = 144;
// gateup (256-thr, 2 CTA/SM): A 128 rows, Wg 64 rows, Wu 64 rows
static constexpr int G_A_O  = 0;
static constexpr int G_BG_O = 128*ROWB;          // 18432
static constexpr int G_BU_O = 192*ROWB;          // 27648
static constexpr int G_STG  = 256*ROWB;          // 36864
// down (512-thr, 1 CTA/SM): A 128 rows, Wd 256 rows
static constexpr int D_A_O  = 0;
static constexpr int D_B_O  = 128*ROWB;          // 18432
static constexpr int D_STG  = 384*ROWB;          // 55296
static constexpr int NST    = 3;

static constexpr int G_NX   = HID / 64;          // 48 GEMM block columns

// ---------------- GEMM1: fused gate/up + SwiGLU -> h fp16 ----------------
// (R11 measured-best GEMM path; blockIdx.x == 48 blocks instead convert Wd
//  int32 -> fp16 for k_down, hidden in gateup's 10-wave scheduling slack)
__global__ __launch_bounds__(256,2)
void k_gateup(const __half* __restrict__ xh,
              const __half* __restrict__ wg, const __half* __restrict__ wu,
              __half* __restrict__ h,
              const int* __restrict__ wd_int, __half* __restrict__ wdh)
{
    // ---- Wd conversion path (64 blocks, one per blockIdx.y) ----
    if (blockIdx.x == G_NX){
        const int n4d = (DIM * HID) / 4;       // 786432
        const int per = n4d / 64;              // 12288
        int base = blockIdx.y * per;
        for (int i = threadIdx.x; i < per; i += 256){
            int idx = base + i;
            int4 v = ((const int4*)wd_int)[idx];
            __half2 a, b;
            a.x = __float2half((float)v.x); a.y = __float2half((float)v.y);
            b.x = __float2half((float)v.z); b.y = __float2half((float)v.w);
            ((__half2*)wdh)[2*idx]   = a;
            ((__half2*)wdh)[2*idx+1] = b;
        }
        return;
    }

    extern __shared__ char sm[];
    const uint32_t sb = smem_u32(sm);
    const int tid = threadIdx.x, lane = tid & 31, wid = tid >> 5;
    const int wm = wid >> 2, wn = wid & 3;
    const int m0 = blockIdx.y * 128, n0 = blockIdx.x * 64;

    const __half* gptr[8];
    uint32_t soff[8];
    #pragma unroll
    for (int j = 0; j < 8; ++j){
        int c = j*256 + tid;
        int row = c >> 3, seg = c & 7;
        const __half* gp; uint32_t so;
        if (row < 128)      { gp = xh + (size_t)(m0+row)*DIM;     so = G_A_O  + row*ROWB; }
        else if (row < 192) { gp = wg + (size_t)(n0+row-128)*DIM; so = G_BG_O + (row-128)*ROWB; }
        else                { gp = wu + (size_t)(n0+row-192)*DIM; so = G_BU_O + (row-192)*ROWB; }
        gptr[j] = gp + seg*8;
        soff[j] = so + seg*16;
    }
    auto load_stage = [&](int s){
        uint32_t st = sb + (uint32_t)(s % NST) * G_STG;
        int k0 = s * 64;
        #pragma unroll
        for (int j = 0; j < 8; ++j) cp_async16(st + soff[j], gptr[j] + k0);
        CP_COMMIT();
    };

    float accg[4][2][4], accu[4][2][4];
    #pragma unroll
    for (int a = 0; a < 4; ++a)
    #pragma unroll
    for (int b = 0; b < 2; ++b)
    #pragma unroll
    for (int c = 0; c < 4; ++c){ accg[a][b][c] = 0.f; accu[a][b][c] = 0.f; }

    load_stage(0);
    load_stage(1);

    const int arow  = lane & 15;
    const int abyte = (lane >> 4) * 16;
    const int brow  = ((lane >> 4) & 1) * 8 + (lane & 7);
    const int bbyte = ((lane >> 3) & 1) * 16;

    const int S = DIM / 64;   // 16
    for (int s = 0; s < S; ++s){
        CP_WAIT(1);
        __syncthreads();
        if (s + 2 < S) load_stage(s + 2);

        uint32_t st = sb + (uint32_t)(s % NST) * G_STG;
        #pragma unroll
        for (int ks = 0; ks < 4; ++ks){
            uint32_t a_[4][4];
            #pragma unroll
            for (int mt = 0; mt < 4; ++mt){
                uint32_t aaddr = st + G_A_O + (uint32_t)((wm*64 + mt*16 + arow)*ROWB + ks*32 + abyte);
                ldsm_x4(a_[mt], aaddr);
            }
            uint32_t bg[2][2], bu[2][2];
            {
                uint32_t baddr = st + G_BG_O + (uint32_t)((wn*16 + brow)*ROWB + ks*32 + bbyte);
                uint32_t t[4];
                ldsm_x4(t, baddr);
                bg[0][0]=t[0]; bg[0][1]=t[1]; bg[1][0]=t[2]; bg[1][1]=t[3];
                ldsm_x4(t, baddr + (G_BU_O - G_BG_O));
                bu[0][0]=t[0]; bu[0][1]=t[1]; bu[1][0]=t[2]; bu[1][1]=t[3];
            }
            #pragma unroll
            for (int mt = 0; mt < 4; ++mt)
            #pragma unroll
            for (int nt = 0; nt < 2; ++nt){
                mma16816(accg[mt][nt], a_[mt], bg[nt]);
                mma16816(accu[mt][nt], a_[mt], bu[nt]);
            }
        }
    }

    const int g = lane >> 2, tig = lane & 3;
    #pragma unroll
    for (int mt = 0; mt < 4; ++mt){
        int rb = m0 + wm*64 + mt*16 + g;
        #pragma unroll
        for (int nt = 0; nt < 2; ++nt){
            int col = n0 + wn*16 + nt*8 + tig*2;
            #pragma unroll
            for (int rr = 0; rr < 2; ++rr){
                int r = rb + rr*8;
                float g0 = accg[mt][nt][rr*2+0] * FSCALE;
                float g1 = accg[mt][nt][rr*2+1] * FSCALE;
                float u0 = accu[mt][nt][rr*2+0] * FSCALE;
                float u1 = accu[mt][nt][rr*2+1] * FSCALE;
                float h0 = g0 / (1.0f + __expf(-g0)) * u0;
                float h1 = g1 / (1.0f + __expf(-g1)) * u1;
                __half2 ph;
                ph.x = __float2half(h0); ph.y = __float2half(h1);
                *(__half2*)(h + (size_t)r*HID + col) = ph;
            }
        }
    }
}

// ---------------- GEMM3: out = SCALE * h @ Wd^T ----------------
// (R10/R14 measured-best: CTA 128m x 256n, 512 thr, warp 32x64, frag dbuf)
__global__ __launch_bounds__(512,1)
void k_down(const __half* __restrict__ h, const __half* __restrict__ wd,
            float* __restrict__ out)
{
    extern __shared__ char sm[];
    const uint32_t sb = smem_u32(sm);
    const int tid = threadIdx.x, lane = tid & 31, wid = tid >> 5;
    const int wm = wid >> 2, wn = wid & 3;
    const int m0 = blockIdx.y * 128, n0 = blockIdx.x * 256;

    const __half* gptr[6];
    uint32_t soff[6];
    #pragma unroll
    for (int j = 0; j < 6; ++j){
        int c = j*512 + tid;
        int row = c >> 3, seg = c & 7;
        const __half* gp; uint32_t so;
        if (row < 128) { gp = h  + (size_t)(m0+row)*HID;     so = D_A_O + row*ROWB; }
        else           { gp = wd + (size_t)(n0+row-128)*HID; so = D_B_O + (row-128)*ROWB; }
        gptr[j] = gp + seg*8;
        soff[j] = so + seg*16;
    }
    auto load_stage = [&](int s){
        uint32_t st = sb + (uint32_t)(s % NST) * D_STG;
        int k0 = s * 64;
        #pragma unroll
        for (int j = 0; j < 6; ++j) cp_async16(st + soff[j], gptr[j] + k0);
        CP_COMMIT();
    };

    float acc[2][8][4];
    #pragma unroll
    for (int a = 0; a < 2; ++a)
    #pragma unroll
    for (int b = 0; b < 8; ++b)
    #pragma unroll
    for (int c = 0; c < 4; ++c) acc[a][b][c] = 0.f;

    const int arow  = lane & 15;
    const int abyte = (lane >> 4) * 16;
    const int brow  = ((lane >> 4) & 1) * 8 + (lane & 7);
    const int bbyte = ((lane >> 3) & 1) * 16;

    uint32_t fa[2][2][4], fbw[2][8][2];

    auto ld_frags = [&](int buf, uint32_t st, int ks){
        #pragma unroll
        for (int mt = 0; mt < 2; ++mt){
            uint32_t aaddr = st + D_A_O + (uint32_t)((wm*32 + mt*16 + arow)*ROWB + ks*32 + abyte);
            ldsm_x4(fa[buf][mt], aaddr);
        }
        #pragma unroll
        for (int p = 0; p < 4; ++p){
            uint32_t baddr = st + D_B_O + (uint32_t)((wn*64 + p*16 + brow)*ROWB + ks*32 + bbyte);
            uint32_t t[4];
            ldsm_x4(t, baddr);
            fbw[buf][2*p][0]=t[0]; fbw[buf][2*p][1]=t[1]; fbw[buf][2*p+1][0]=t[2]; fbw[buf][2*p+1][1]=t[3];
        }
    };
    auto do_mma = [&](int buf){
        #pragma unroll
        for (int mt = 0; mt < 2; ++mt)
        #pragma unroll
        for (int nt = 0; nt < 8; ++nt)
            mma16816(acc[mt][nt], fa[buf][mt], fbw[buf][nt]);
    };

    load_stage(0);
    load_stage(1);
    load_stage(2);
    CP_WAIT(2);
    __syncthreads();
    ld_frags(0, sb, 0);

    const int S = HID / 64;   // 48
    for (int s = 0; s < S; ++s){
        uint32_t stc = sb + (uint32_t)(s % NST) * D_STG;
        uint32_t stn = sb + (uint32_t)((s + 1) % NST) * D_STG;
        ld_frags(1, stc, 1); do_mma(0);
        ld_frags(0, stc, 2); do_mma(1);
        ld_frags(1, stc, 3); do_mma(0);
        if (s < S - 1){
            if (s + 3 <= S) { CP_WAIT(1); } else { CP_WAIT(0); }
            __syncthreads();
        }
        if (s + 3 < S) load_stage(s + 3);
        if (s < S - 1) ld_frags(0, stn, 0);
        do_mma(1);
    }

    const int g = lane >> 2, tig = lane & 3;
    #pragma unroll
    for (int mt = 0; mt < 2; ++mt){
        int rb = m0 + wm*32 + mt*16 + g;
        #pragma unroll
        for (int nt = 0; nt < 8; ++nt){
            int col = n0 + wn*64 + nt*8 + tig*2;
            #pragma unroll
            for (int rr = 0; rr < 2; ++rr){
                int r = rb + rr*8;
                float2 o;
                o.x = acc[mt][nt][rr*2+0] * FSCALE;
                o.y = acc[mt][nt][rr*2+1] * FSCALE;
                *(float2*)(out + (size_t)r*DIM + col) = o;
            }
        }
    }
}

// ---------------- launch ----------------
extern "C" void kernel_launch(void* const* d_in, const int* in_sizes, int n_in,
                              void* d_out, int out_size)
{
    const float* x  = (const float*)d_in[0];
    const int*   wg = (const int*)d_in[1];
    const int*   wu = (const int*)d_in[2];
    const int*   wd = (const int*)d_in[3];
    float*       out = (float*)d_out;

    const int M = in_sizes[0] / DIM;   // 8192

    __half *wgh, *wuh, *wdh, *xh, *hh;
    cudaGetSymbolAddress((void**)&wgh, g_wg);
    cudaGetSymbolAddress((void**)&wuh, g_wu);
    cudaGetSymbolAddress((void**)&wdh, g_wd);
    cudaGetSymbolAddress((void**)&xh,  g_xh);
    cudaGetSymbolAddress((void**)&hh,  g_h);

    // prep: x cast + wg/wu conversion in ONE launch (concurrent HBM streams)
    {
        int nx4 = (M * DIM) / 4;       // 2097152
        int nw4 = (HID * DIM) / 4;     // 786432
        dim3 gp((nx4 + 255) / 256, 3); // (8192, 3); y>=1 blocks beyond nw4 exit
        k_prep<<<gp, 256>>>(x, wg, wu, xh, wgh, wuh, nx4, nw4);
    }

    const int SM1 = NST * G_STG;   // 110592
    const int SM3 = NST * D_STG;   // 165888
    cudaFuncSetAttribute(k_gateup, cudaFuncAttributeMaxDynamicSharedMemorySize, SM1);
    cudaFuncSetAttribute(k_down,   cudaFuncAttributeMaxDynamicSharedMemorySize, SM3);

    // gateup GEMM + hidden Wd conversion (extra grid column x == 48)
    dim3 g1(G_NX + 1, M / 128);    // (49, 64)
    k_gateup<<<g1, 256, SM1>>>(xh, wgh, wuh, hh, wd, wdh);

    dim3 g3(DIM / 256, M / 128);   // (4, 64)
    k_down<<<g3, 512, SM3>>>(hh, wdh, out);
}

// round 16
// speedup vs baseline: 1.0135x; 1.0135x over previous
#include <cuda_runtime.h>
#include <cuda_fp16.h>
#include <math.h>
#include <stdint.h>

#define DIM  1024
#define HID  3072
#define MTOK 8192
#define FSCALE (1.0f/127.0f)

// ---------------- device scratch ----------------
__device__ __align__(16) __half g_wg[(size_t)HID*DIM];
__device__ __align__(16) __half g_wu[(size_t)HID*DIM];
__device__ __align__(16) __half g_wd[(size_t)DIM*HID];
__device__ __align__(16) __half g_xh[(size_t)MTOK*DIM];
__device__ __align__(16) __half g_h [(size_t)MTOK*HID];

// ---------------- helpers ----------------
__device__ __forceinline__ uint32_t smem_u32(const void* p){
    uint32_t a;
    asm("{ .reg .u64 t; cvta.to.shared.u64 t, %1; cvt.u32.u64 %0, t; }" : "=r"(a) : "l"(p));
    return a;
}
__device__ __forceinline__ void cp_async16(uint32_t s, const void* g){
    asm volatile("cp.async.cg.shared.global [%0], [%1], 16;" :: "r"(s), "l"(g));
}
#define CP_COMMIT() asm volatile("cp.async.commit_group;" ::: "memory")
#define CP_WAIT(N)  asm volatile("cp.async.wait_group %0;" :: "n"(N) : "memory")

__device__ __forceinline__ void ldsm_x4(uint32_t* r, uint32_t a){
    asm volatile("ldmatrix.sync.aligned.m8n8.x4.shared.b16 {%0,%1,%2,%3}, [%4];"
        : "=r"(r[0]),"=r"(r[1]),"=r"(r[2]),"=r"(r[3]) : "r"(a));
}
__device__ __forceinline__ void mma16816(float* d, const uint32_t* a, const uint32_t* b){
    asm volatile("mma.sync.aligned.m16n8k16.row.col.f32.f16.f16.f32 "
        "{%0,%1,%2,%3},{%4,%5,%6,%7},{%8,%9},{%0,%1,%2,%3};"
        : "+f"(d[0]),"+f"(d[1]),"+f"(d[2]),"+f"(d[3])
        : "r"(a[0]),"r"(a[1]),"r"(a[2]),"r"(a[3]), "r"(b[0]),"r"(b[1]));
}

// ---------------- prep kernels (2x16B per thread for MLP) ----------------
__global__ void k_convw3(const int* __restrict__ w0, const int* __restrict__ w1,
                         const int* __restrict__ w2,
                         __half* __restrict__ o0, __half* __restrict__ o1,
                         __half* __restrict__ o2, int n4)
{
    const int* w = (blockIdx.y == 0) ? w0 : (blockIdx.y == 1) ? w1 : w2;
    __half*    o = (blockIdx.y == 0) ? o0 : (blockIdx.y == 1) ? o1 : o2;
    int i = (blockIdx.x * blockDim.x + threadIdx.x) * 2;
    if (i + 1 < n4){
        int4 v0 = ((const int4*)w)[i];
        int4 v1 = ((const int4*)w)[i+1];
        __half2 a0, b0, a1, b1;
        a0.x = __float2half((float)v0.x); a0.y = __float2half((float)v0.y);
        b0.x = __float2half((float)v0.z); b0.y = __float2half((float)v0.w);
        a1.x = __float2half((float)v1.x); a1.y = __float2half((float)v1.y);
        b1.x = __float2half((float)v1.z); b1.y = __float2half((float)v1.w);
        ((__half2*)o)[2*i]   = a0;
        ((__half2*)o)[2*i+1] = b0;
        ((__half2*)o)[2*i+2] = a1;
        ((__half2*)o)[2*i+3] = b1;
    }
}
__global__ void k_castx(const float* __restrict__ x, __half* __restrict__ o, int n4){
    int i = (blockIdx.x * blockDim.x + threadIdx.x) * 2;
    if (i + 1 < n4){
        float4 v0 = ((const float4*)x)[i];
        float4 v1 = ((const float4*)x)[i+1];
        __half2 a0, b0, a1, b1;
        a0.x = __float2half(v0.x); a0.y = __float2half(v0.y);
        b0.x = __float2half(v0.z); b0.y = __float2half(v0.w);
        a1.x = __float2half(v1.x); a1.y = __float2half(v1.y);
        b1.x = __float2half(v1.z); b1.y = __float2half(v1.w);
        ((__half2*)o)[2*i]   = a0;
        ((__half2*)o)[2*i+1] = b0;
        ((__half2*)o)[2*i+2] = a1;
        ((__half2*)o)[2*i+3] = b1;
    }
}

// ---------------- GEMM config ----------------
// BK=64 fp16 (128B data rows + 16B pad = 144B stride, conflict-free ldmatrix).
static constexpr int ROWB = 144;
// gateup (256-thr, 2 CTA/SM): A 128 rows, Wg 64 rows, Wu 64 rows
static constexpr int G_A_O  = 0;
static constexpr int G_BG_O = 128*ROWB;          // 18432
static constexpr int G_BU_O = 192*ROWB;          // 27648
static constexpr int G_STG  = 256*ROWB;          // 36864
// down (512-thr, 1 CTA/SM): A 128 rows, Wd 256 rows
static constexpr int D_A_O  = 0;
static constexpr int D_B_O  = 128*ROWB;          // 18432
static constexpr int D_STG  = 384*ROWB;          // 55296
static constexpr int NST    = 3;

// ---------------- GEMM1: fused gate/up + SwiGLU -> h fp16 ----------------
// (R11/R14 measured-best: CTA 128m x (64g+64u), 8 warps (2m x 4n), 2 CTAs/SM)
__global__ __launch_bounds__(256,2)
void k_gateup(const __half* __restrict__ xh,
              const __half* __restrict__ wg, const __half* __restrict__ wu,
              __half* __restrict__ h)
{
    extern __shared__ char sm[];
    const uint32_t sb = smem_u32(sm);
    const int tid = threadIdx.x, lane = tid & 31, wid = tid >> 5;
    const int wm = wid >> 2, wn = wid & 3;
    const int m0 = blockIdx.y * 128, n0 = blockIdx.x * 64;

    const __half* gptr[8];
    uint32_t soff[8];
    #pragma unroll
    for (int j = 0; j < 8; ++j){
        int c = j*256 + tid;
        int row = c >> 3, seg = c & 7;
        const __half* gp; uint32_t so;
        if (row < 128)      { gp = xh + (size_t)(m0+row)*DIM;     so = G_A_O  + row*ROWB; }
        else if (row < 192) { gp = wg + (size_t)(n0+row-128)*DIM; so = G_BG_O + (row-128)*ROWB; }
        else                { gp = wu + (size_t)(n0+row-192)*DIM; so = G_BU_O + (row-192)*ROWB; }
        gptr[j] = gp + seg*8;
        soff[j] = so + seg*16;
    }
    auto load_stage = [&](int s){
        uint32_t st = sb + (uint32_t)(s % NST) * G_STG;
        int k0 = s * 64;
        #pragma unroll
        for (int j = 0; j < 8; ++j) cp_async16(st + soff[j], gptr[j] + k0);
        CP_COMMIT();
    };

    float accg[4][2][4], accu[4][2][4];
    #pragma unroll
    for (int a = 0; a < 4; ++a)
    #pragma unroll
    for (int b = 0; b < 2; ++b)
    #pragma unroll
    for (int c = 0; c < 4; ++c){ accg[a][b][c] = 0.f; accu[a][b][c] = 0.f; }

    load_stage(0);
    load_stage(1);

    const int arow  = lane & 15;
    const int abyte = (lane >> 4) * 16;
    const int brow  = ((lane >> 4) & 1) * 8 + (lane & 7);
    const int bbyte = ((lane >> 3) & 1) * 16;

    const int S = DIM / 64;   // 16
    for (int s = 0; s < S; ++s){
        CP_WAIT(1);
        __syncthreads();
        if (s + 2 < S) load_stage(s + 2);

        uint32_t st = sb + (uint32_t)(s % NST) * G_STG;
        #pragma unroll
        for (int ks = 0; ks < 4; ++ks){
            uint32_t a_[4][4];
            #pragma unroll
            for (int mt = 0; mt < 4; ++mt){
                uint32_t aaddr = st + G_A_O + (uint32_t)((wm*64 + mt*16 + arow)*ROWB + ks*32 + abyte);
                ldsm_x4(a_[mt], aaddr);
            }
            uint32_t bg[2][2], bu[2][2];
            {
                uint32_t baddr = st + G_BG_O + (uint32_t)((wn*16 + brow)*ROWB + ks*32 + bbyte);
                uint32_t t[4];
                ldsm_x4(t, baddr);
                bg[0][0]=t[0]; bg[0][1]=t[1]; bg[1][0]=t[2]; bg[1][1]=t[3];
                ldsm_x4(t, baddr + (G_BU_O - G_BG_O));
                bu[0][0]=t[0]; bu[0][1]=t[1]; bu[1][0]=t[2]; bu[1][1]=t[3];
            }
            #pragma unroll
            for (int mt = 0; mt < 4; ++mt)
            #pragma unroll
            for (int nt = 0; nt < 2; ++nt){
                mma16816(accg[mt][nt], a_[mt], bg[nt]);
                mma16816(accu[mt][nt], a_[mt], bu[nt]);
            }
        }
    }

    const int g = lane >> 2, tig = lane & 3;
    #pragma unroll
    for (int mt = 0; mt < 4; ++mt){
        int rb = m0 + wm*64 + mt*16 + g;
        #pragma unroll
        for (int nt = 0; nt < 2; ++nt){
            int col = n0 + wn*16 + nt*8 + tig*2;
            #pragma unroll
            for (int rr = 0; rr < 2; ++rr){
                int r = rb + rr*8;
                float g0 = accg[mt][nt][rr*2+0] * FSCALE;
                float g1 = accg[mt][nt][rr*2+1] * FSCALE;
                float u0 = accu[mt][nt][rr*2+0] * FSCALE;
                float u1 = accu[mt][nt][rr*2+1] * FSCALE;
                float h0 = g0 / (1.0f + __expf(-g0)) * u0;
                float h1 = g1 / (1.0f + __expf(-g1)) * u1;
                __half2 ph;
                ph.x = __float2half(h0); ph.y = __float2half(h1);
                *(__half2*)(h + (size_t)r*HID + col) = ph;
            }
        }
    }
}

// ---------------- GEMM3: out = SCALE * h @ Wd^T ----------------
// (R10/R14 measured-best: CTA 128m x 256n, 512 thr, warp 32x64, frag dbuf)
__global__ __launch_bounds__(512,1)
void k_down(const __half* __restrict__ h, const __half* __restrict__ wd,
            float* __restrict__ out)
{
    extern __shared__ char sm[];
    const uint32_t sb = smem_u32(sm);
    const int tid = threadIdx.x, lane = tid & 31, wid = tid >> 5;
    const int wm = wid >> 2, wn = wid & 3;
    const int m0 = blockIdx.y * 128, n0 = blockIdx.x * 256;

    const __half* gptr[6];
    uint32_t soff[6];
    #pragma unroll
    for (int j = 0; j < 6; ++j){
        int c = j*512 + tid;
        int row = c >> 3, seg = c & 7;
        const __half* gp; uint32_t so;
        if (row < 128) { gp = h  + (size_t)(m0+row)*HID;     so = D_A_O + row*ROWB; }
        else           { gp = wd + (size_t)(n0+row-128)*HID; so = D_B_O + (row-128)*ROWB; }
        gptr[j] = gp + seg*8;
        soff[j] = so + seg*16;
    }
    auto load_stage = [&](int s){
        uint32_t st = sb + (uint32_t)(s % NST) * D_STG;
        int k0 = s * 64;
        #pragma unroll
        for (int j = 0; j < 6; ++j) cp_async16(st + soff[j], gptr[j] + k0);
        CP_COMMIT();
    };

    float acc[2][8][4];
    #pragma unroll
    for (int a = 0; a < 2; ++a)
    #pragma unroll
    for (int b = 0; b < 8; ++b)
    #pragma unroll
    for (int c = 0; c < 4; ++c) acc[a][b][c] = 0.f;

    const int arow  = lane & 15;
    const int abyte = (lane >> 4) * 16;
    const int brow  = ((lane >> 4) & 1) * 8 + (lane & 7);
    const int bbyte = ((lane >> 3) & 1) * 16;

    uint32_t fa[2][2][4], fbw[2][8][2];

    auto ld_frags = [&](int buf, uint32_t st, int ks){
        #pragma unroll
        for (int mt = 0; mt < 2; ++mt){
            uint32_t aaddr = st + D_A_O + (uint32_t)((wm*32 + mt*16 + arow)*ROWB + ks*32 + abyte);
            ldsm_x4(fa[buf][mt], aaddr);
        }
        #pragma unroll
        for (int p = 0; p < 4; ++p){
            uint32_t baddr = st + D_B_O + (uint32_t)((wn*64 + p*16 + brow)*ROWB + ks*32 + bbyte);
            uint32_t t[4];
            ldsm_x4(t, baddr);
            fbw[buf][2*p][0]=t[0]; fbw[buf][2*p][1]=t[1]; fbw[buf][2*p+1][0]=t[2]; fbw[buf][2*p+1][1]=t[3];
        }
    };
    auto do_mma = [&](int buf){
        #pragma unroll
        for (int mt = 0; mt < 2; ++mt)
        #pragma unroll
        for (int nt = 0; nt < 8; ++nt)
            mma16816(acc[mt][nt], fa[buf][mt], fbw[buf][nt]);
    };

    load_stage(0);
    load_stage(1);
    load_stage(2);
    CP_WAIT(2);
    __syncthreads();
    ld_frags(0, sb, 0);

    const int S = HID / 64;   // 48
    for (int s = 0; s < S; ++s){
        uint32_t stc = sb + (uint32_t)(s % NST) * D_STG;
        uint32_t stn = sb + (uint32_t)((s + 1) % NST) * D_STG;
        ld_frags(1, stc, 1); do_mma(0);
        ld_frags(0, stc, 2); do_mma(1);
        ld_frags(1, stc, 3); do_mma(0);
        if (s < S - 1){
            if (s + 3 <= S) { CP_WAIT(1); } else { CP_WAIT(0); }
            __syncthreads();
        }
        if (s + 3 < S) load_stage(s + 3);
        if (s < S - 1) ld_frags(0, stn, 0);
        do_mma(1);
    }

    const int g = lane >> 2, tig = lane & 3;
    #pragma unroll
    for (int mt = 0; mt < 2; ++mt){
        int rb = m0 + wm*32 + mt*16 + g;
        #pragma unroll
        for (int nt = 0; nt < 8; ++nt){
            int col = n0 + wn*64 + nt*8 + tig*2;
            #pragma unroll
            for (int rr = 0; rr < 2; ++rr){
                int r = rb + rr*8;
                float2 o;
                o.x = acc[mt][nt][rr*2+0] * FSCALE;
                o.y = acc[mt][nt][rr*2+1] * FSCALE;
                *(float2*)(out + (size_t)r*DIM + col) = o;
            }
        }
    }
}

// ---------------- launch ----------------
extern "C" void kernel_launch(void* const* d_in, const int* in_sizes, int n_in,
                              void* d_out, int out_size)
{
    const float* x  = (const float*)d_in[0];
    const int*   wg = (const int*)d_in[1];
    const int*   wu = (const int*)d_in[2];
    const int*   wd = (const int*)d_in[3];
    float*       out = (float*)d_out;

    const int M = in_sizes[0] / DIM;   // 8192

    __half *wgh, *wuh, *wdh, *xh, *hh;
    cudaGetSymbolAddress((void**)&wgh, g_wg);
    cudaGetSymbolAddress((void**)&wuh, g_wu);
    cudaGetSymbolAddress((void**)&wdh, g_wd);
    cudaGetSymbolAddress((void**)&xh,  g_xh);
    cudaGetSymbolAddress((void**)&hh,  g_h);

    {
        int n4 = (HID * DIM) / 4;
        dim3 gw((n4/2 + 255) / 256, 3);
        k_convw3<<<gw, 256>>>(wg, wu, wd, wgh, wuh, wdh, n4);
        int nx4 = (M * DIM) / 4;
        k_castx<<<(nx4/2 + 255) / 256, 256>>>(x, xh, nx4);
    }

    const int SM1 = NST * G_STG;   // 110592
    const int SM3 = NST * D_STG;   // 165888
    cudaFuncSetAttribute(k_gateup, cudaFuncAttributeMaxDynamicSharedMemorySize, SM1);
    cudaFuncSetAttribute(k_down,   cudaFuncAttributeMaxDynamicSharedMemorySize, SM3);

    dim3 g1(HID / 64, M / 128);    // (48, 64)
    k_gateup<<<g1, 256, SM1>>>(xh, wgh, wuh, hh);

    dim3 g3(DIM / 256, M / 128);   // (4, 64)
    k_down<<<g3, 512, SM3>>>(hh, wdh, out);
}

// round 17
// speedup vs baseline: 1.0262x; 1.0125x over previous
#include <cuda_runtime.h>
#include <cuda_fp16.h>
#include <math.h>
#include <stdint.h>

#define DIM  1024
#define HID  3072
#define MTOK 8192
#define FSCALE (1.0f/127.0f)

// ---------------- device scratch ----------------
__device__ __align__(16) __half g_wg[(size_t)HID*DIM];
__device__ __align__(16) __half g_wu[(size_t)HID*DIM];
__device__ __align__(16) __half g_wd[(size_t)DIM*HID];
__device__ __align__(16) __half g_xh[(size_t)MTOK*DIM];
__device__ __align__(16) __half g_h [(size_t)MTOK*HID];

// ---------------- helpers ----------------
__device__ __forceinline__ uint32_t smem_u32(const void* p){
    uint32_t a;
    asm("{ .reg .u64 t; cvta.to.shared.u64 t, %1; cvt.u32.u64 %0, t; }" : "=r"(a) : "l"(p));
    return a;
}
__device__ __forceinline__ void cp_async16(uint32_t s, const void* g){
    asm volatile("cp.async.cg.shared.global [%0], [%1], 16;" :: "r"(s), "l"(g));
}
#define CP_COMMIT() asm volatile("cp.async.commit_group;" ::: "memory")
#define CP_WAIT(N)  asm volatile("cp.async.wait_group %0;" :: "n"(N) : "memory")

__device__ __forceinline__ void ldsm_x4(uint32_t* r, uint32_t a){
    asm volatile("ldmatrix.sync.aligned.m8n8.x4.shared.b16 {%0,%1,%2,%3}, [%4];"
        : "=r"(r[0]),"=r"(r[1]),"=r"(r[2]),"=r"(r[3]) : "r"(a));
}
__device__ __forceinline__ void mma16816(float* d, const uint32_t* a, const uint32_t* b){
    asm volatile("mma.sync.aligned.m16n8k16.row.col.f32.f16.f16.f32 "
        "{%0,%1,%2,%3},{%4,%5,%6,%7},{%8,%9},{%0,%1,%2,%3};"
        : "+f"(d[0]),"+f"(d[1]),"+f"(d[2]),"+f"(d[3])
        : "r"(a[0]),"r"(a[1]),"r"(a[2]),"r"(a[3]), "r"(b[0]),"r"(b[1]));
}

// ---------------- prep kernels (2x16B per thread for MLP) ----------------
__global__ void k_convw3(const int* __restrict__ w0, const int* __restrict__ w1,
                         const int* __restrict__ w2,
                         __half* __restrict__ o0, __half* __restrict__ o1,
                         __half* __restrict__ o2, int n4)
{
    const int* w = (blockIdx.y == 0) ? w0 : (blockIdx.y == 1) ? w1 : w2;
    __half*    o = (blockIdx.y == 0) ? o0 : (blockIdx.y == 1) ? o1 : o2;
    int i = (blockIdx.x * blockDim.x + threadIdx.x) * 2;
    if (i + 1 < n4){
        int4 v0 = ((const int4*)w)[i];
        int4 v1 = ((const int4*)w)[i+1];
        __half2 a0, b0, a1, b1;
        a0.x = __float2half((float)v0.x); a0.y = __float2half((float)v0.y);
        b0.x = __float2half((float)v0.z); b0.y = __float2half((float)v0.w);
        a1.x = __float2half((float)v1.x); a1.y = __float2half((float)v1.y);
        b1.x = __float2half((float)v1.z); b1.y = __float2half((float)v1.w);
        ((__half2*)o)[2*i]   = a0;
        ((__half2*)o)[2*i+1] = b0;
        ((__half2*)o)[2*i+2] = a1;
        ((__half2*)o)[2*i+3] = b1;
    }
}
__global__ void k_castx(const float* __restrict__ x, __half* __restrict__ o, int n4){
    int i = (blockIdx.x * blockDim.x + threadIdx.x) * 2;
    if (i + 1 < n4){
        float4 v0 = ((const float4*)x)[i];
        float4 v1 = ((const float4*)x)[i+1];
        __half2 a0, b0, a1, b1;
        a0.x = __float2half(v0.x); a0.y = __float2half(v0.y);
        b0.x = __float2half(v0.z); b0.y = __float2half(v0.w);
        a1.x = __float2half(v1.x); a1.y = __float2half(v1.y);
        b1.x = __float2half(v1.z); b1.y = __float2half(v1.w);
        ((__half2*)o)[2*i]   = a0;
        ((__half2*)o)[2*i+1] = b0;
        ((__half2*)o)[2*i+2] = a1;
        ((__half2*)o)[2*i+3] = b1;
    }
}

// ---------------- GEMM config ----------------
// BK=64 fp16 (128B data rows + 16B pad = 144B stride, conflict-free ldmatrix).
static constexpr int ROWB = 144;
// gateup (256-thr, 2 CTA/SM): A 128 rows, Wg 64 rows, Wu 64 rows
static constexpr int G_A_O  = 0;
static constexpr int G_BG_O = 128*ROWB;          // 18432
static constexpr int G_BU_O = 192*ROWB;          // 27648
static constexpr int G_STG  = 256*ROWB;          // 36864
// down (256-thr, 2 CTA/SM): A 128 rows, Wd 128 rows
static constexpr int D_A_O  = 0;
static constexpr int D_B_O  = 128*ROWB;          // 18432
static constexpr int D_STG  = 256*ROWB;          // 36864
static constexpr int NST    = 3;

// ---------------- GEMM1: fused gate/up + SwiGLU -> h fp16 ----------------
// (R11/R16 measured-best: CTA 128m x (64g+64u), 8 warps (2m x 4n), 2 CTAs/SM)
__global__ __launch_bounds__(256,2)
void k_gateup(const __half* __restrict__ xh,
              const __half* __restrict__ wg, const __half* __restrict__ wu,
              __half* __restrict__ h)
{
    extern __shared__ char sm[];
    const uint32_t sb = smem_u32(sm);
    const int tid = threadIdx.x, lane = tid & 31, wid = tid >> 5;
    const int wm = wid >> 2, wn = wid & 3;
    const int m0 = blockIdx.y * 128, n0 = blockIdx.x * 64;

    const __half* gptr[8];
    uint32_t soff[8];
    #pragma unroll
    for (int j = 0; j < 8; ++j){
        int c = j*256 + tid;
        int row = c >> 3, seg = c & 7;
        const __half* gp; uint32_t so;
        if (row < 128)      { gp = xh + (size_t)(m0+row)*DIM;     so = G_A_O  + row*ROWB; }
        else if (row < 192) { gp = wg + (size_t)(n0+row-128)*DIM; so = G_BG_O + (row-128)*ROWB; }
        else                { gp = wu + (size_t)(n0+row-192)*DIM; so = G_BU_O + (row-192)*ROWB; }
        gptr[j] = gp + seg*8;
        soff[j] = so + seg*16;
    }
    auto load_stage = [&](int s){
        uint32_t st = sb + (uint32_t)(s % NST) * G_STG;
        int k0 = s * 64;
        #pragma unroll
        for (int j = 0; j < 8; ++j) cp_async16(st + soff[j], gptr[j] + k0);
        CP_COMMIT();
    };

    float accg[4][2][4], accu[4][2][4];
    #pragma unroll
    for (int a = 0; a < 4; ++a)
    #pragma unroll
    for (int b = 0; b < 2; ++b)
    #pragma unroll
    for (int c = 0; c < 4; ++c){ accg[a][b][c] = 0.f; accu[a][b][c] = 0.f; }

    load_stage(0);
    load_stage(1);

    const int arow  = lane & 15;
    const int abyte = (lane >> 4) * 16;
    const int brow  = ((lane >> 4) & 1) * 8 + (lane & 7);
    const int bbyte = ((lane >> 3) & 1) * 16;

    const int S = DIM / 64;   // 16
    for (int s = 0; s < S; ++s){
        CP_WAIT(1);
        __syncthreads();
        if (s + 2 < S) load_stage(s + 2);

        uint32_t st = sb + (uint32_t)(s % NST) * G_STG;
        #pragma unroll
        for (int ks = 0; ks < 4; ++ks){
            uint32_t a_[4][4];
            #pragma unroll
            for (int mt = 0; mt < 4; ++mt){
                uint32_t aaddr = st + G_A_O + (uint32_t)((wm*64 + mt*16 + arow)*ROWB + ks*32 + abyte);
                ldsm_x4(a_[mt], aaddr);
            }
            uint32_t bg[2][2], bu[2][2];
            {
                uint32_t baddr = st + G_BG_O + (uint32_t)((wn*16 + brow)*ROWB + ks*32 + bbyte);
                uint32_t t[4];
                ldsm_x4(t, baddr);
                bg[0][0]=t[0]; bg[0][1]=t[1]; bg[1][0]=t[2]; bg[1][1]=t[3];
                ldsm_x4(t, baddr + (G_BU_O - G_BG_O));
                bu[0][0]=t[0]; bu[0][1]=t[1]; bu[1][0]=t[2]; bu[1][1]=t[3];
            }
            #pragma unroll
            for (int mt = 0; mt < 4; ++mt)
            #pragma unroll
            for (int nt = 0; nt < 2; ++nt){
                mma16816(accg[mt][nt], a_[mt], bg[nt]);
                mma16816(accu[mt][nt], a_[mt], bu[nt]);
            }
        }
    }

    const int g = lane >> 2, tig = lane & 3;
    #pragma unroll
    for (int mt = 0; mt < 4; ++mt){
        int rb = m0 + wm*64 + mt*16 + g;
        #pragma unroll
        for (int nt = 0; nt < 2; ++nt){
            int col = n0 + wn*16 + nt*8 + tig*2;
            #pragma unroll
            for (int rr = 0; rr < 2; ++rr){
                int r = rb + rr*8;
                float g0 = accg[mt][nt][rr*2+0] * FSCALE;
                float g1 = accg[mt][nt][rr*2+1] * FSCALE;
                float u0 = accu[mt][nt][rr*2+0] * FSCALE;
                float u1 = accu[mt][nt][rr*2+1] * FSCALE;
                float h0 = g0 / (1.0f + __expf(-g0)) * u0;
                float h1 = g1 / (1.0f + __expf(-g1)) * u1;
                __half2 ph;
                ph.x = __float2half(h0); ph.y = __float2half(h1);
                *(__half2*)(h + (size_t)r*HID + col) = ph;
            }
        }
    }
}

// ---------------- GEMM3: out = SCALE * h @ Wd^T ----------------
// NEW: CTA 128m x 128n, 256 thr, 8 warps (4m x 2n), warp 32m x 64n,
// fragment double-buffered, 2 CTAs/SM (barrier desync + frag dbuf combined).
__global__ __launch_bounds__(256,2)
void k_down(const __half* __restrict__ h, const __half* __restrict__ wd,
            float* __restrict__ out)
{
    extern __shared__ char sm[];
    const uint32_t sb = smem_u32(sm);
    const int tid = threadIdx.x, lane = tid & 31, wid = tid >> 5;
    const int wm = wid >> 1, wn = wid & 1;      // 4m x 2n
    const int m0 = blockIdx.y * 128, n0 = blockIdx.x * 128;

    // 256 rows x 128B per stage, 256 thr -> 8 chunks of 16B per thread
    const __half* gptr[8];
    uint32_t soff[8];
    #pragma unroll
    for (int j = 0; j < 8; ++j){
        int c = j*256 + tid;          // 0..2047
        int row = c >> 3, seg = c & 7;
        const __half* gp; uint32_t so;
        if (row < 128) { gp = h  + (size_t)(m0+row)*HID;     so = D_A_O + row*ROWB; }
        else           { gp = wd + (size_t)(n0+row-128)*HID; so = D_B_O + (row-128)*ROWB; }
        gptr[j] = gp + seg*8;
        soff[j] = so + seg*16;
    }
    auto load_stage = [&](int s){
        uint32_t st = sb + (uint32_t)(s % NST) * D_STG;
        int k0 = s * 64;
        #pragma unroll
        for (int j = 0; j < 8; ++j) cp_async16(st + soff[j], gptr[j] + k0);
        CP_COMMIT();
    };

    float acc[2][8][4];
    #pragma unroll
    for (int a = 0; a < 2; ++a)
    #pragma unroll
    for (int b = 0; b < 8; ++b)
    #pragma unroll
    for (int c = 0; c < 4; ++c) acc[a][b][c] = 0.f;

    const int arow  = lane & 15;
    const int abyte = (lane >> 4) * 16;
    const int brow  = ((lane >> 4) & 1) * 8 + (lane & 7);
    const int bbyte = ((lane >> 3) & 1) * 16;

    uint32_t fa[2][2][4], fbw[2][8][2];

    auto ld_frags = [&](int buf, uint32_t st, int ks){
        #pragma unroll
        for (int mt = 0; mt < 2; ++mt){
            uint32_t aaddr = st + D_A_O + (uint32_t)((wm*32 + mt*16 + arow)*ROWB + ks*32 + abyte);
            ldsm_x4(fa[buf][mt], aaddr);
        }
        #pragma unroll
        for (int p = 0; p < 4; ++p){
            uint32_t baddr = st + D_B_O + (uint32_t)((wn*64 + p*16 + brow)*ROWB + ks*32 + bbyte);
            uint32_t t[4];
            ldsm_x4(t, baddr);
            fbw[buf][2*p][0]=t[0]; fbw[buf][2*p][1]=t[1]; fbw[buf][2*p+1][0]=t[2]; fbw[buf][2*p+1][1]=t[3];
        }
    };
    auto do_mma = [&](int buf){
        #pragma unroll
        for (int mt = 0; mt < 2; ++mt)
        #pragma unroll
        for (int nt = 0; nt < 8; ++nt)
            mma16816(acc[mt][nt], fa[buf][mt], fbw[buf][nt]);
    };

    load_stage(0);
    load_stage(1);
    load_stage(2);
    CP_WAIT(2);
    __syncthreads();
    ld_frags(0, sb, 0);

    const int S = HID / 64;   // 48
    for (int s = 0; s < S; ++s){
        uint32_t stc = sb + (uint32_t)(s % NST) * D_STG;
        uint32_t stn = sb + (uint32_t)((s + 1) % NST) * D_STG;
        ld_frags(1, stc, 1); do_mma(0);
        ld_frags(0, stc, 2); do_mma(1);
        ld_frags(1, stc, 3); do_mma(0);
        if (s < S - 1){
            if (s + 3 <= S) { CP_WAIT(1); } else { CP_WAIT(0); }
            __syncthreads();
        }
        if (s + 3 < S) load_stage(s + 3);
        if (s < S - 1) ld_frags(0, stn, 0);
        do_mma(1);
    }

    const int g = lane >> 2, tig = lane & 3;
    #pragma unroll
    for (int mt = 0; mt < 2; ++mt){
        int rb = m0 + wm*32 + mt*16 + g;
        #pragma unroll
        for (int nt = 0; nt < 8; ++nt){
            int col = n0 + wn*64 + nt*8 + tig*2;
            #pragma unroll
            for (int rr = 0; rr < 2; ++rr){
                int r = rb + rr*8;
                float2 o;
                o.x = acc[mt][nt][rr*2+0] * FSCALE;
                o.y = acc[mt][nt][rr*2+1] * FSCALE;
                *(float2*)(out + (size_t)r*DIM + col) = o;
            }
        }
    }
}

// ---------------- launch ----------------
extern "C" void kernel_launch(void* const* d_in, const int* in_sizes, int n_in,
                              void* d_out, int out_size)
{
    const float* x  = (const float*)d_in[0];
    const int*   wg = (const int*)d_in[1];
    const int*   wu = (const int*)d_in[2];
    const int*   wd = (const int*)d_in[3];
    float*       out = (float*)d_out;

    const int M = in_sizes[0] / DIM;   // 8192

    __half *wgh, *wuh, *wdh, *xh, *hh;
    cudaGetSymbolAddress((void**)&wgh, g_wg);
    cudaGetSymbolAddress((void**)&wuh, g_wu);
    cudaGetSymbolAddress((void**)&wdh, g_wd);
    cudaGetSymbolAddress((void**)&xh,  g_xh);
    cudaGetSymbolAddress((void**)&hh,  g_h);

    {
        int n4 = (HID * DIM) / 4;
        dim3 gw((n4/2 + 255) / 256, 3);
        k_convw3<<<gw, 256>>>(wg, wu, wd, wgh, wuh, wdh, n4);
        int nx4 = (M * DIM) / 4;
        k_castx<<<(nx4/2 + 255) / 256, 256>>>(x, xh, nx4);
    }

    const int SM1 = NST * G_STG;   // 110592
    const int SM3 = NST * D_STG;   // 110592
    cudaFuncSetAttribute(k_gateup, cudaFuncAttributeMaxDynamicSharedMemorySize, SM1);
    cudaFuncSetAttribute(k_down,   cudaFuncAttributeMaxDynamicSharedMemorySize, SM3);

    dim3 g1(HID / 64, M / 128);    // (48, 64)
    k_gateup<<<g1, 256, SM1>>>(xh, wgh, wuh, hh);

    dim3 g3(DIM / 128, M / 128);   // (8, 64)
    k_down<<<g3, 256, SM3>>>(hh, wdh, out);
}